// round 2
// baseline (speedup 1.0000x reference)
#include <cuda_runtime.h>

// neigh_Conv: out[n,c,h,w] = b[c] + sum_{k<8} W[c,k] * x[n,c+k,h,w]
// x: (16, 200, 128, 128) f32 -> out: (16, 193, 128, 128) f32
//
// R2: channel-chunked streaming. R1 was latency-bound (DRAM 30%, occ 20%,
// 256 CTAs). Split the output-channel sweep into 4 chunks (halo re-read of
// 7 planes per extra chunk, +10% input traffic) -> 1024 CTAs, 4x warps,
// 4x chip-level MLP.

#define HW4    4096   // 128*128/4 float4 per plane
#define CIN    200
#define OUTC   193
#define RING   16
#define NCHUNK 4
#define CHG    49     // output channels per chunk (last chunk: 46)
#define LOOPN  56     // static trip count, multiple of 8, >= CHG+7

__global__ __launch_bounds__(256)
void neigh_conv_kernel(const float4* __restrict__ x,
                       const float4* __restrict__ W4,   // 193*2 float4
                       const float*  __restrict__ b,
                       float4* __restrict__ out) {
    __shared__ float4 sW[OUTC * 2];
    __shared__ float  sB[OUTC];

    const int t = threadIdx.x;
    for (int i = t; i < OUTC * 2; i += blockDim.x) sW[i] = W4[i];
    for (int i = t; i < OUTC;     i += blockDim.x) sB[i] = b[i];
    __syncthreads();

    const int gid = blockIdx.x * blockDim.x + t;     // 0 .. 65535
    const int n   = gid >> 12;
    const int pos = gid & 4095;

    const int cbase = blockIdx.y * CHG;              // first output channel
    const int nout  = min(CHG, OUTC - cbase);        // 49 or 46
    const int nin   = nout + 7;                      // input planes this chunk

    const float4* xin = x   + ((size_t)n * CIN  + cbase) * HW4 + pos;
    float4*       op  = out + ((size_t)n * OUTC + cbase) * HW4 + pos;

    // Register ring: before local iter oc it holds x[cbase+oc .. +14].
    float4 win[RING];
#pragma unroll
    for (int i = 0; i < RING - 1; ++i)
        win[i] = __ldcs(xin + (size_t)i * HW4);

#pragma unroll 8
    for (int oc = 0; oc < LOOPN; ++oc) {
        if (oc < nin - (RING - 1))
            win[(oc + RING - 1) & (RING - 1)] =
                __ldcs(xin + (size_t)(oc + RING - 1) * HW4);

        if (oc < nout) {
            const int c = cbase + oc;
            const float4 w0 = sW[c * 2];
            const float4 w1 = sW[c * 2 + 1];
            const float  wk[8] = {w0.x, w0.y, w0.z, w0.w,
                                  w1.x, w1.y, w1.z, w1.w};
            const float bb = sB[c];
            float4 acc = make_float4(bb, bb, bb, bb);
#pragma unroll
            for (int k = 0; k < 8; ++k) {
                const float4 xv = win[(oc + k) & (RING - 1)];
                acc.x = fmaf(wk[k], xv.x, acc.x);
                acc.y = fmaf(wk[k], xv.y, acc.y);
                acc.z = fmaf(wk[k], xv.z, acc.z);
                acc.w = fmaf(wk[k], xv.w, acc.w);
            }
            __stcs(op + (size_t)oc * HW4, acc);
        }
    }
}

extern "C" void kernel_launch(void* const* d_in, const int* in_sizes, int n_in,
                              void* d_out, int out_size) {
    const float4* x  = (const float4*)d_in[0];
    const float4* W4 = (const float4*)d_in[1];
    const float*  b  = (const float*)d_in[2];
    float4* out = (float4*)d_out;

    dim3 grid(65536 / 256, NCHUNK);   // (n,pos) x channel-chunk
    neigh_conv_kernel<<<grid, 256>>>(x, W4, b, out);
}

// round 3
// speedup vs baseline: 1.4750x; 1.4750x over previous
#include <cuda_runtime.h>

// neigh_Conv: out[n,c,h,w] = b[c] + sum_{k<8} W[c,k] * x[n,c+k,h,w]
// x: (16, 200, 128, 128) f32 -> out: (16, 193, 128, 128) f32
//
// R3: register-resident ring with PROVABLY static indices.
// R1/R2 failure: with unroll-by-8 the ring index (oc+j)&15 was runtime
// (oc multiple of 8, not 16) -> ring demoted to local memory -> bound on
// L1 local traffic. Fix: outer loop steps by 16, inner 16 fully unrolled,
// so every ring index is a compile-time constant.

#define HW4    4096   // 128*128/4 float4 per plane
#define CIN    200
#define OUTC   193
#define NCHUNK 4
#define CHG    49     // output channels per chunk (last: 46)
#define LOOPN  64     // multiple of 16, >= CHG

__global__ __launch_bounds__(256)
void neigh_conv_kernel(const float4* __restrict__ x,
                       const float4* __restrict__ W4,   // 193*2 float4
                       const float*  __restrict__ b,
                       float4* __restrict__ out) {
    __shared__ float4 sW[OUTC * 2];
    __shared__ float  sB[OUTC];

    const int t = threadIdx.x;
    for (int i = t; i < OUTC * 2; i += blockDim.x) sW[i] = W4[i];
    for (int i = t; i < OUTC;     i += blockDim.x) sB[i] = b[i];
    __syncthreads();

    const int gid = blockIdx.x * blockDim.x + t;     // 0 .. 65535
    const int n   = gid >> 12;
    const int pos = gid & 4095;

    const int cbase = blockIdx.y * CHG;
    const int nout  = min(CHG, OUTC - cbase);        // 49 or 46
    const int nin   = nout + 7;                      // planes needed

    const float4* xin = x   + ((size_t)n * CIN  + cbase) * HW4 + pos;
    float4*       op  = out + ((size_t)n * OUTC + cbase) * HW4 + pos;

    // Ring invariant: at iteration oc, win[(oc+j)&15] holds plane cbase+oc+j
    // for j = 0..14. All indices below are compile-time constants.
    float4 win[16];
#pragma unroll
    for (int i = 0; i < 15; ++i)
        win[i] = __ldcs(xin + (size_t)i * HW4);

    for (int ocb = 0; ocb < LOOPN; ocb += 16) {
#pragma unroll
        for (int u = 0; u < 16; ++u) {
            const int oc = ocb + u;                  // ocb runtime, u static

            // Prefetch plane oc+15 (consumed starting at iteration oc+8).
            if (oc < nin - 15)
                win[(u + 15) & 15] = __ldcs(xin + (size_t)(oc + 15) * HW4);

            if (oc < nout) {
                const int c = cbase + oc;
                const float4 w0 = sW[c * 2];
                const float4 w1 = sW[c * 2 + 1];
                const float  wk[8] = {w0.x, w0.y, w0.z, w0.w,
                                      w1.x, w1.y, w1.z, w1.w};
                const float bb = sB[c];
                float4 acc = make_float4(bb, bb, bb, bb);
#pragma unroll
                for (int k = 0; k < 8; ++k) {
                    const float4 xv = win[(u + k) & 15];   // static index
                    acc.x = fmaf(wk[k], xv.x, acc.x);
                    acc.y = fmaf(wk[k], xv.y, acc.y);
                    acc.z = fmaf(wk[k], xv.z, acc.z);
                    acc.w = fmaf(wk[k], xv.w, acc.w);
                }
                __stcs(op + (size_t)oc * HW4, acc);
            }
        }
    }
}

extern "C" void kernel_launch(void* const* d_in, const int* in_sizes, int n_in,
                              void* d_out, int out_size) {
    const float4* x  = (const float4*)d_in[0];
    const float4* W4 = (const float4*)d_in[1];
    const float*  b  = (const float*)d_in[2];
    float4* out = (float4*)d_out;

    dim3 grid(65536 / 256, NCHUNK);   // (n,pos) x channel-chunk
    neigh_conv_kernel<<<grid, 256>>>(x, W4, b, out);
}

// round 4
// speedup vs baseline: 2.4527x; 1.6628x over previous
#include <cuda_runtime.h>

// neigh_Conv: out[n,c,h,w] = b[c] + sum_{k<8} W[c,k] * x[n,c+k,h,w]
// x: (16, 200, 128, 128) f32 -> out: (16, 193, 128, 128) f32
//
// R4: cp.async staging + accumulator ring.
// R3 was MLP-collapsed: register-ring loads aliased onto few scoreboard
// slots -> effective 1 load in flight per warp -> DRAM 40%. Fix: track
// loads with cp.async commit-groups (depth 6) into a private smem stage
// per thread; compute via an 8-slot accumulator ring (static indices).

#define HW4    4096   // 128*128/4 float4 per plane
#define CIN    200
#define OUTC   193
#define NCHUNK 4
#define CHG    49     // output channels per chunk (last: 46)
#define CHGP   56     // padded chunk stride for sWk
#define LOOPN  56     // multiple of 8, >= max nin (= 56)
#define STAGES 8
#define DEPTH  6      // planes in flight per thread

__global__ __launch_bounds__(256)
void neigh_conv_kernel(const float* __restrict__ x,
                       const float* __restrict__ Wg,   // (193, 8) row-major
                       const float* __restrict__ b,
                       float4* __restrict__ out) {
    __shared__ float4 stg[STAGES * 256];   // [stage][tid], 32 KB
    __shared__ float  sWk[8 * CHGP];       // transposed: sWk[k*CHGP + ocl]
    __shared__ float  sB[CHGP];

    const int t     = threadIdx.x;
    const int cbase = blockIdx.y * CHG;
    const int nout  = min(CHG, OUTC - cbase);   // 49 or 46
    const int nin   = nout + 7;

    for (int i = t; i < nout * 8; i += 256) {
        int ocl = i >> 3, k = i & 7;
        sWk[k * CHGP + ocl] = Wg[(cbase + ocl) * 8 + k];
    }
    for (int i = t; i < nout; i += 256) sB[i] = b[cbase + i];
    __syncthreads();

    const int gid = blockIdx.x * 256 + t;    // 0..65535
    const int n   = gid >> 12;
    const int pos = gid & 4095;

    const float4* xin = (const float4*)x + ((size_t)n * CIN  + cbase) * HW4 + pos;
    float4*       op  = out              + ((size_t)n * OUTC + cbase) * HW4 + pos;

    const unsigned sbase = (unsigned)__cvta_generic_to_shared(&stg[t]);
    // stage s for this thread lives at sbase + s*(256*16)

    // Prologue: planes 0..DEPTH-1, one commit group each.
#pragma unroll
    for (int p = 0; p < DEPTH; ++p) {
        unsigned sa = sbase + p * (256 * 16);
        const float4* ga = xin + (size_t)p * HW4;
        asm volatile("cp.async.cg.shared.global [%0], [%1], 16;\n"
                     :: "r"(sa), "l"(ga));
        asm volatile("cp.async.commit_group;\n" ::: "memory");
    }

    float4 acc[8];   // acc[oc & 7] accumulates output channel oc

    for (int cb = 0; cb < LOOPN; cb += 8) {
#pragma unroll
        for (int u = 0; u < 8; ++u) {
            const int c = cb + u;                 // input plane index (c&7 == u)

            // Guarantee plane c has landed (<=5 newer groups pending).
            asm volatile("cp.async.wait_group 5;\n" ::: "memory");

            float4 xv;
            {
                unsigned sa = sbase + u * (256 * 16);
                asm volatile("ld.shared.v4.f32 {%0,%1,%2,%3}, [%4];"
                             : "=f"(xv.x), "=f"(xv.y), "=f"(xv.z), "=f"(xv.w)
                             : "r"(sa));
            }

            // Refill pipeline: plane c+DEPTH into stage (u+DEPTH)&7
            // (that slot held plane c-2, consumed 2 iterations ago).
            if (c + DEPTH < nin) {
                unsigned sa = sbase + ((u + DEPTH) & 7) * (256 * 16);
                const float4* ga = xin + (size_t)(c + DEPTH) * HW4;
                asm volatile("cp.async.cg.shared.global [%0], [%1], 16;\n"
                             :: "r"(sa), "l"(ga));
            }
            // Always commit (possibly empty group) to keep the count exact.
            asm volatile("cp.async.commit_group;\n" ::: "memory");

            // k=7 term completes output oc = c-7 -> emit.
            if ((unsigned)(c - 7) < (unsigned)nout) {
                const float w = sWk[7 * CHGP + (c - 7)];
                const int s = (u + 1) & 7;        // (c-7)&7, static
                acc[s].x = fmaf(w, xv.x, acc[s].x);
                acc[s].y = fmaf(w, xv.y, acc[s].y);
                acc[s].z = fmaf(w, xv.z, acc[s].z);
                acc[s].w = fmaf(w, xv.w, acc[s].w);
                __stcs(op + (size_t)(c - 7) * HW4, acc[s]);
            }
            // Middle terms k = 6..1.
#pragma unroll
            for (int k = 6; k >= 1; --k) {
                if ((unsigned)(c - k) < (unsigned)nout) {
                    const float w = sWk[k * CHGP + (c - k)];
                    const int s = (u - k) & 7;    // static
                    acc[s].x = fmaf(w, xv.x, acc[s].x);
                    acc[s].y = fmaf(w, xv.y, acc[s].y);
                    acc[s].z = fmaf(w, xv.z, acc[s].z);
                    acc[s].w = fmaf(w, xv.w, acc[s].w);
                }
            }
            // k=0: start output oc = c (init slot with bias + first term).
            if (c < nout) {
                const float w  = sWk[c];
                const float bb = sB[c];
                acc[u].x = fmaf(w, xv.x, bb);
                acc[u].y = fmaf(w, xv.y, bb);
                acc[u].z = fmaf(w, xv.z, bb);
                acc[u].w = fmaf(w, xv.w, bb);
            }
        }
    }
}

extern "C" void kernel_launch(void* const* d_in, const int* in_sizes, int n_in,
                              void* d_out, int out_size) {
    const float* x  = (const float*)d_in[0];
    const float* Wg = (const float*)d_in[1];
    const float* b  = (const float*)d_in[2];
    float4* out = (float4*)d_out;

    dim3 grid(65536 / 256, NCHUNK);
    neigh_conv_kernel<<<grid, 256>>>(x, Wg, b, out);
}

// round 5
// speedup vs baseline: 2.4581x; 1.0022x over previous
#include <cuda_runtime.h>

// neigh_Conv: out[n,c,h,w] = b[c] + sum_{k<8} W[c,k] * x[n,c+k,h,w]
// x: (16, 200, 128, 128) f32 -> out: (16, 193, 128, 128) f32
//
// R5: guard-free inner loop via zero-padded diagonal weights.
// R4 was issue-bound (issue 75%, alu 52%): 8 runtime bounds checks + 8
// scalar LDS per plane. Fix: dW[c][k] = W[c-k][k] (0 outside range) built
// once in smem -> 2 LDS.128 per plane, zero ISETP in the accumulation.
// Keep cp.async depth-6 staging (DRAM was 70%), accumulator ring.

#define HW4    4096   // 128*128/4 float4 per plane
#define CIN    200
#define OUTC   193
#define NCHUNK 4
#define CHG    49     // output channels per chunk (last: 46)
#define LOOPN  56     // multiple of 8, >= max nin (=56)
#define DEPTH  6

__global__ __launch_bounds__(256)
void neigh_conv_kernel(const float* __restrict__ x,
                       const float* __restrict__ Wg,   // (193, 8) row-major
                       const float* __restrict__ b,
                       float4* __restrict__ out) {
    __shared__ float4 stg[8 * 256];        // [slot][tid], 32 KB
    __shared__ float4 sDW[LOOPN * 2];      // dW[c] = 8 floats (2 float4)
    __shared__ float  sB[LOOPN];

    const int t     = threadIdx.x;
    const int cbase = blockIdx.y * CHG;
    const int nout  = min(CHG, OUTC - cbase);   // 49 or 46
    const int nin   = nout + 7;

    // dW[c][k] = W[c-k][k] if 0 <= c-k < nout else 0  (c = 0..55)
    float* sDWf = (float*)sDW;
    for (int i = t; i < LOOPN * 8; i += 256) {
        const int c = i >> 3, k = i & 7;
        const int oc = c - k;
        sDWf[i] = ((unsigned)oc < (unsigned)nout) ? Wg[(cbase + oc) * 8 + k] : 0.0f;
    }
    for (int i = t; i < LOOPN; i += 256)
        sB[i] = (i < nout) ? b[cbase + i] : 0.0f;
    __syncthreads();

    const int gid = blockIdx.x * 256 + t;    // 0..65535
    const int n   = gid >> 12;
    const int pos = gid & 4095;

    const float4* xin = (const float4*)x + ((size_t)n * CIN  + cbase) * HW4 + pos;
    float4*       op  = out              + ((size_t)n * OUTC + cbase) * HW4 + pos;

    const unsigned sbase = (unsigned)__cvta_generic_to_shared(&stg[t]);
    // slot s lives at sbase + s*4096 bytes

    // Prologue: planes 0..DEPTH-1, one commit group each.
#pragma unroll
    for (int p = 0; p < DEPTH; ++p) {
        const unsigned sa = sbase + p * 4096;
        const float4* ga = xin + (size_t)p * HW4;
        asm volatile("cp.async.cg.shared.global [%0], [%1], 16;\n"
                     :: "r"(sa), "l"(ga));
        asm volatile("cp.async.commit_group;\n" ::: "memory");
    }

    float4 acc[8];   // acc[oc & 7] accumulates output channel oc

    for (int cb = 0; cb < LOOPN; cb += 8) {
        const float4* gpre = xin + (size_t)(cb + DEPTH) * HW4;  // refill base
        float4*       oemt = op  + (size_t)(cb - 7)     * HW4;  // emit base

#pragma unroll
        for (int u = 0; u < 8; ++u) {
            const int c = cb + u;

            asm volatile("cp.async.wait_group 5;\n" ::: "memory");

            float4 xv;
            {
                const unsigned sa = sbase + u * 4096;
                asm volatile("ld.shared.v4.f32 {%0,%1,%2,%3}, [%4];"
                             : "=f"(xv.x), "=f"(xv.y), "=f"(xv.z), "=f"(xv.w)
                             : "r"(sa));
            }

            // Refill plane c+DEPTH into slot (u+DEPTH)&7 (held plane c-2).
            if (c + DEPTH < nin) {
                const unsigned sa = sbase + ((u + DEPTH) & 7) * 4096;
                const float4* ga = gpre + (size_t)u * HW4;
                asm volatile("cp.async.cg.shared.global [%0], [%1], 16;\n"
                             :: "r"(sa), "l"(ga));
            }
            asm volatile("cp.async.commit_group;\n" ::: "memory");

            const float4 w0 = sDW[c * 2];       // k = 0..3
            const float4 w1 = sDW[c * 2 + 1];   // k = 4..7
            const float  bb = sB[c];

            // k=7 completes output c-7 (slot (u+1)&7), then emit.
            {
                const int s = (u + 1) & 7;
                acc[s].x = fmaf(w1.w, xv.x, acc[s].x);
                acc[s].y = fmaf(w1.w, xv.y, acc[s].y);
                acc[s].z = fmaf(w1.w, xv.z, acc[s].z);
                acc[s].w = fmaf(w1.w, xv.w, acc[s].w);
                if ((unsigned)(c - 7) < (unsigned)nout)
                    __stcs(oemt + (size_t)u * HW4, acc[s]);
            }
            // k = 6..1 (weights zero outside valid range -> no guards).
            {
                const int s = (u + 2) & 7;
                acc[s].x = fmaf(w1.z, xv.x, acc[s].x);
                acc[s].y = fmaf(w1.z, xv.y, acc[s].y);
                acc[s].z = fmaf(w1.z, xv.z, acc[s].z);
                acc[s].w = fmaf(w1.z, xv.w, acc[s].w);
            }
            {
                const int s = (u + 3) & 7;
                acc[s].x = fmaf(w1.y, xv.x, acc[s].x);
                acc[s].y = fmaf(w1.y, xv.y, acc[s].y);
                acc[s].z = fmaf(w1.y, xv.z, acc[s].z);
                acc[s].w = fmaf(w1.y, xv.w, acc[s].w);
            }
            {
                const int s = (u + 4) & 7;
                acc[s].x = fmaf(w1.x, xv.x, acc[s].x);
                acc[s].y = fmaf(w1.x, xv.y, acc[s].y);
                acc[s].z = fmaf(w1.x, xv.z, acc[s].z);
                acc[s].w = fmaf(w1.x, xv.w, acc[s].w);
            }
            {
                const int s = (u + 5) & 7;
                acc[s].x = fmaf(w0.w, xv.x, acc[s].x);
                acc[s].y = fmaf(w0.w, xv.y, acc[s].y);
                acc[s].z = fmaf(w0.w, xv.z, acc[s].z);
                acc[s].w = fmaf(w0.w, xv.w, acc[s].w);
            }
            {
                const int s = (u + 6) & 7;
                acc[s].x = fmaf(w0.z, xv.x, acc[s].x);
                acc[s].y = fmaf(w0.z, xv.y, acc[s].y);
                acc[s].z = fmaf(w0.z, xv.z, acc[s].z);
                acc[s].w = fmaf(w0.z, xv.w, acc[s].w);
            }
            {
                const int s = (u + 7) & 7;
                acc[s].x = fmaf(w0.y, xv.x, acc[s].x);
                acc[s].y = fmaf(w0.y, xv.y, acc[s].y);
                acc[s].z = fmaf(w0.y, xv.z, acc[s].z);
                acc[s].w = fmaf(w0.y, xv.w, acc[s].w);
            }
            // k=0: (re)init slot u for output c with bias + first term.
            acc[u].x = fmaf(w0.x, xv.x, bb);
            acc[u].y = fmaf(w0.x, xv.y, bb);
            acc[u].z = fmaf(w0.x, xv.z, bb);
            acc[u].w = fmaf(w0.x, xv.w, bb);
        }
    }
}

extern "C" void kernel_launch(void* const* d_in, const int* in_sizes, int n_in,
                              void* d_out, int out_size) {
    const float* x  = (const float*)d_in[0];
    const float* Wg = (const float*)d_in[1];
    const float* b  = (const float*)d_in[2];
    float4* out = (float4*)d_out;

    dim3 grid(65536 / 256, NCHUNK);
    neigh_conv_kernel<<<grid, 256>>>(x, Wg, b, out);
}